// round 16
// baseline (speedup 1.0000x reference)
#include <cuda_runtime.h>
#include <cuda_bf16.h>

// Problem constants
#define S_TOK 8192
#define D_DIM 2048
#define E_EXP 64
#define CAP   128
#define SEC   (S_TOK * E_EXP * CAP)   // 67108864
#define LAST_F 134217728              // tail float index; out_size = LAST_F+1
#define NKS    4                      // split-K slices
#define KSLICE (D_DIM / NKS)          // 512
#define ZBYTES_PER_BLOCK 2097152u     // 2MB zeroed per block (256 blocks)
#define ZCHUNK 16384u                 // bulk-store chunk (16KB)
#define ASTRIDE 36
#define NBLK   (NKS * 64)             // 256 blocks total

// dynamic SMEM: [zero buf 4096 floats][sA 2*128*36][sB 2*64*36]
#define ZBUF_FLOATS 4096
#define SA_OFF ZBUF_FLOATS
#define SB_OFF (ZBUF_FLOATS + 2 * 128 * ASTRIDE)
#define SMEM_FLOATS (ZBUF_FLOATS + 2 * 128 * ASTRIDE + 2 * 64 * ASTRIDE)
#define SMEM_BYTES (SMEM_FLOATS * 4)  // 71680

// -------------------- device scratch --------------------
__device__ float g_part[S_TOK * NKS * E_EXP];      // 8MB partial logits [s][ks][e]
__device__ int2  g_pack[S_TOK];                    // {gate bits, expert<<8|rank}
__device__ int   g_cntp[64 * E_EXP];               // [mtile][expert] counts
__device__ float g_me_part[64 * E_EXP];            // [mtile][expert] gate col sums
__device__ int   g_tilectr[64];                    // per-mtile ks completion
__device__ int   g_zctr;                           // grid barrier counter
__device__ int   g_phase;                          // grid barrier sense

// -------------------- packed fp32 FMA (FFMA2) --------------------
__device__ __forceinline__ void ffma2(float2& d, const float2& a, const float2& b) {
    unsigned long long dd = *(const unsigned long long*)&d;
    unsigned long long aa = *(const unsigned long long*)&a;
    unsigned long long bb = *(const unsigned long long*)&b;
    asm("fma.rn.f32x2 %0, %1, %2, %0;" : "+l"(dd) : "l"(aa), "l"(bb));
    d = *(float2*)&dd;
}

__device__ __forceinline__ unsigned smem_u32(const void* p) {
    unsigned a;
    asm("{ .reg .u64 t; cvta.to.shared.u64 t, %1; cvt.u32.u64 %0, t; }"
        : "=r"(a) : "l"(p));
    return a;
}

// ---- ONE kernel: split-K GEMM + paced TMA zero + softmax + grid barrier
//      + parallel scatter (SMEM-staged prefix) ----
__global__ __launch_bounds__(256, 2) void k_all(const float* __restrict__ x,
                                                const float* __restrict__ wg,
                                                float* __restrict__ out) {
    extern __shared__ float smem[];
    float* zbuf = smem;
    float* sA = smem + SA_OFF;
    float* sB = smem + SB_OFF;
    __shared__ int wcnt[4 * 64];       // per-warp per-expert counts (epilogue)
    __shared__ int spref[64];          // this block's mtile prefix (scatter)

    const int tid = threadIdx.x;
    const int lane = tid & 31, w = tid >> 5;
    const int tx = tid & 15, ty = tid >> 4;
    const int ks = blockIdx.x;
    const int mtile = blockIdx.y;
    const int m0 = mtile * 128;
    const int kbase = ks * KSLICE;
    const int b = mtile * NKS + ks;    // linear block id 0..255
    char* zdst = (char*)out + (size_t)b * ZBYTES_PER_BLOCK;

    // zero the TMA staging buffer (stays zero through the zero phase)
#pragma unroll
    for (int r = 0; r < 4; r++)
        *(float4*)&zbuf[(tid + r * 256) * 4] = make_float4(0.f, 0.f, 0.f, 0.f);

    // prologue loads: tile 0
    const int mA = tid >> 3, kqA = tid & 7;
    float4 pa[4], pb[2];
#pragma unroll
    for (int r = 0; r < 4; r++)
        pa[r] = *(const float4*)(x + (size_t)(m0 + mA + r * 32) * D_DIM + kbase + kqA * 4);
#pragma unroll
    for (int r = 0; r < 2; r++)
        pb[r] = *(const float4*)(wg + (size_t)(mA + r * 32) * D_DIM + kbase + kqA * 4);
#pragma unroll
    for (int r = 0; r < 4; r++)
        *(float4*)&sA[(mA + r * 32) * ASTRIDE + kqA * 4] = pa[r];
#pragma unroll
    for (int r = 0; r < 2; r++)
        *(float4*)&sB[(mA + r * 32) * ASTRIDE + kqA * 4] = pb[r];
    __syncthreads();

    const unsigned zsrc = smem_u32(zbuf);
    if (tid == 0) asm volatile("fence.proxy.async;" ::: "memory");

    float2 acc[8][4];
#pragma unroll
    for (int i = 0; i < 8; i++)
#pragma unroll
        for (int j = 0; j < 4; j++) acc[i][j] = make_float2(0.f, 0.f);

    for (int it = 0; it < KSLICE / 32; it++) {
        const int buf = it & 1;
        float* cA = sA + buf * 128 * ASTRIDE;
        float* cB = sB + buf * 64 * ASTRIDE;

        // paced zeros: 8 x 16KB per iteration (128 chunks total = 2MB)
        if (tid == 0) {
#pragma unroll
            for (int c = 0; c < 8; c++) {
                char* g = zdst + (size_t)(it * 8 + c) * ZCHUNK;
                asm volatile(
                    "cp.async.bulk.global.shared::cta.bulk_group [%0], [%1], %2;"
                    :: "l"(g), "r"(zsrc), "n"(ZCHUNK) : "memory");
            }
        }

        // prefetch next tile
        if (it < KSLICE / 32 - 1) {
            const int kn = kbase + (it + 1) * 32;
#pragma unroll
            for (int r = 0; r < 4; r++)
                pa[r] = *(const float4*)(x + (size_t)(m0 + mA + r * 32) * D_DIM + kn + kqA * 4);
#pragma unroll
            for (int r = 0; r < 2; r++)
                pb[r] = *(const float4*)(wg + (size_t)(mA + r * 32) * D_DIM + kn + kqA * 4);
        }

#pragma unroll
        for (int kk8 = 0; kk8 < 8; kk8++) {
            float4 b4[4];
#pragma unroll
            for (int j = 0; j < 4; j++)
                b4[j] = *(const float4*)&cB[(tx + 16 * j) * ASTRIDE + kk8 * 4];
#pragma unroll
            for (int i = 0; i < 8; i++) {
                float4 a4 = *(const float4*)&cA[(ty + 16 * i) * ASTRIDE + kk8 * 4];
                const float2* ap = (const float2*)&a4;
#pragma unroll
                for (int j = 0; j < 4; j++) {
                    const float2* bp = (const float2*)&b4[j];
                    ffma2(acc[i][j], ap[0], bp[0]);
                    ffma2(acc[i][j], ap[1], bp[1]);
                }
            }
        }

        if (it < KSLICE / 32 - 1) {
            float* nA = sA + (buf ^ 1) * 128 * ASTRIDE;
            float* nB = sB + (buf ^ 1) * 64 * ASTRIDE;
#pragma unroll
            for (int r = 0; r < 4; r++)
                *(float4*)&nA[(mA + r * 32) * ASTRIDE + kqA * 4] = pa[r];
#pragma unroll
            for (int r = 0; r < 2; r++)
                *(float4*)&nB[(mA + r * 32) * ASTRIDE + kqA * 4] = pb[r];
        }
        __syncthreads();
    }

    if (tid == 0) asm volatile("cp.async.bulk.commit_group;" ::: "memory");

    // write partial logits: g_part[(m0+t)*4 + ks][e]
#pragma unroll
    for (int i = 0; i < 8; i++) {
        int t = m0 + ty + 16 * i;
        float* dst = g_part + ((size_t)t * NKS + ks) * E_EXP;
#pragma unroll
        for (int j = 0; j < 4; j++)
            dst[tx + 16 * j] = acc[i][j].x + acc[i][j].y;
    }

    // ---- softmax + rank epilogue: last ks-block of this mtile ----
    __shared__ int s_last;
    if (tid == 0) {
        __threadfence();
        int done = atomicAdd(&g_tilectr[mtile], 1);
        s_last = (done == NKS - 1);
        if (s_last) g_tilectr[mtile] = 0;   // reset for graph replay
    }
    __syncthreads();
    if (s_last) {
        float* sg = smem + ZBUF_FLOATS;          // 128*65 floats (over sA/sB)
        float* sq = sg + 128 * 65;               // 4*64 partial col sums
        int am = 255;                            // dummy for tid>=128 warps
        float gate = 0.f;
        wcnt[tid] = 0;
        if (tid < 128) {
            int t = m0 + tid;
            const float4* p = (const float4*)g_part + (size_t)t * 64;
            float row[64];
#pragma unroll
            for (int e4 = 0; e4 < 16; e4++) {
                float4 v0 = __ldcg(p + e4);
                float4 v1 = __ldcg(p + 16 + e4);
                float4 v2 = __ldcg(p + 32 + e4);
                float4 v3 = __ldcg(p + 48 + e4);
                row[4 * e4 + 0] = v0.x + v1.x + v2.x + v3.x;
                row[4 * e4 + 1] = v0.y + v1.y + v2.y + v3.y;
                row[4 * e4 + 2] = v0.z + v1.z + v2.z + v3.z;
                row[4 * e4 + 3] = v0.w + v1.w + v2.w + v3.w;
            }
            float mx = row[0];
            am = 0;
#pragma unroll
            for (int e = 1; e < 64; e++)
                if (row[e] > mx) { mx = row[e]; am = e; }
            float sum = 0.f;
#pragma unroll
            for (int e = 0; e < 64; e++) { row[e] = expf(row[e] - mx); sum += row[e]; }
            gate = 1.0f / sum;
#pragma unroll
            for (int e = 0; e < 64; e++) sg[tid * 65 + e] = row[e] * gate;
        }
        __syncthreads();
        // col sums for me (all 256 threads)
        {
            int col = tid & 63, q = tid >> 6;
            float cs = 0.f;
#pragma unroll 8
            for (int r = 0; r < 32; r++)
                cs += sg[(q * 32 + r) * 65 + col];
            sq[q * 64 + col] = cs;
        }
        // warp-level rank via match_any (warps 4-7 run on dummy am)
        unsigned mmask = __match_any_sync(0xffffffffu, am);
        int rin = __popc(mmask & ((1u << lane) - 1u));
        if (tid < 128 && rin == 0) wcnt[w * 64 + am] = __popc(mmask);
        __syncthreads();
        if (tid < 128) {
            int base = 0;
#pragma unroll
            for (int w2 = 0; w2 < 4; w2++)
                if (w2 < w) base += wcnt[w2 * 64 + am];
            g_pack[m0 + tid] = make_int2(__float_as_int(gate),
                                         (am << 8) | (base + rin));
        }
        if (tid < 64) {
            g_me_part[mtile * 64 + tid] =
                sq[tid] + sq[64 + tid] + sq[128 + tid] + sq[192 + tid];
            g_cntp[mtile * 64 + tid] =
                wcnt[tid] + wcnt[64 + tid] + wcnt[128 + tid] + wcnt[192 + tid];
        }
    }

    // ---- grid-wide sense-reversal barrier (all 256 blocks co-resident) ----
    // Arrival implies: this block's TMA zeros complete + its epilogue visible.
    if (tid == 0) {
        asm volatile("cp.async.bulk.wait_group 0;" ::: "memory");
        __threadfence();
        int ph = *(volatile int*)&g_phase;
        int old = atomicAdd(&g_zctr, 1);
        if (old == NBLK - 1) {
            g_zctr = 0;                       // safe: all arrived
            __threadfence();
            *(volatile int*)&g_phase = ph ^ 1;
        } else {
            while (*(volatile int*)&g_phase == ph) __nanosleep(32);
        }
    }
    __syncthreads();

    // ---- parallel scatter: 32 tokens per block, SMEM-staged counts ----
    {
        // cooperative stage of g_cntp (4096 ints) into zbuf region:
        // one batched LDG round-trip instead of per-thread serial walks.
        int* scnt = (int*)smem;
        {
            const int4* src = (const int4*)g_cntp;
            int4* dst4 = (int4*)smem;
#pragma unroll
            for (int r = 0; r < 4; r++)
                dst4[tid + r * 256] = __ldcg(src + tid + r * 256);
        }
        __syncthreads();

        const int M = b >> 2;              // mtile owning tokens b*32..b*32+31
        if (tid < 64) {
            int run = 0;
#pragma unroll 8
            for (int m = 0; m < M; m++) run += scnt[m * 64 + tid];
            spref[tid] = run;
        }
        __syncthreads();
        if (tid < 32) {
            int s = b * 32 + tid;
            int2 pk = __ldcg((const int2*)g_pack + s);
            int e = pk.y >> 8;
            int loc = spref[e] + (pk.y & 255);
            if (loc < CAP) {
                size_t off = (size_t)s * (E_EXP * CAP) + e * CAP + loc;
                out[1 + off] = __int_as_float(pk.x);
                out[1 + (size_t)SEC + off] = 1.0f;
            }
        }
        // block 0: l_aux + tail element (me_part staged through SMEM)
        if (b == 0) {
            float* sme = smem + SA_OFF;     // free region (4096 floats)
            {
                const float4* src = (const float4*)g_me_part;
                float4* dst4 = (float4*)sme;
#pragma unroll
                for (int r = 0; r < 4; r++)
                    dst4[tid + r * 256] = __ldcg(src + tid + r * 256);
            }
            __syncthreads();
            float v = 0.f;
            if (tid < 64) {
                float me = 0.f;
                int cnt = 0;
#pragma unroll 8
                for (int m = 0; m < 64; m++) {
                    me += sme[m * 64 + tid];
                    cnt += scnt[m * 64 + tid];
                }
                v = me * (float)cnt;
            }
#pragma unroll
            for (int o = 16; o; o >>= 1) v += __shfl_down_sync(0xffffffffu, v, o);
            __shared__ float red[2];
            if ((tid & 31) == 0 && tid < 64) red[tid >> 5] = v;
            __syncthreads();
            if (tid == 0)
                out[0] = (red[0] + red[1]) * (64.0f / (8192.0f * 8192.0f));
            if (tid == 255) out[LAST_F] = 0.0f;
        }
    }
}

// -------------------- launch: ONE kernel --------------------
extern "C" void kernel_launch(void* const* d_in, const int* in_sizes, int n_in,
                              void* d_out, int out_size) {
    const float* x  = (const float*)d_in[0];
    const float* wg = (const float*)d_in[1];
    float* out = (float*)d_out;

    static bool attr_set = false;
    if (!attr_set) {
        cudaFuncSetAttribute(k_all,
                             cudaFuncAttributeMaxDynamicSharedMemorySize,
                             SMEM_BYTES);
        attr_set = true;
    }

    k_all<<<dim3(NKS, 64), 256, SMEM_BYTES>>>(x, wg, out);
}

// round 17
// speedup vs baseline: 1.0311x; 1.0311x over previous
#include <cuda_runtime.h>
#include <cuda_bf16.h>

// Problem constants
#define S_TOK 8192
#define D_DIM 2048
#define E_EXP 64
#define CAP   128
#define SEC   (S_TOK * E_EXP * CAP)   // 67108864
#define LAST_F 134217728              // tail float index; out_size = LAST_F+1
#define NKS    4                      // split-K slices
#define KSLICE (D_DIM / NKS)          // 512
#define ZBYTES_PER_BLOCK 2097152u     // 2MB zeroed per block (256 blocks)
#define ZCHUNK 16384u                 // bulk-store chunk (16KB)
#define ASTRIDE 36
#define NBLK   (NKS * 64)             // 256 blocks total

// dynamic SMEM: [zero buf 4096 floats][sA 2*128*36][sB 2*64*36]
#define ZBUF_FLOATS 4096
#define SA_OFF ZBUF_FLOATS
#define SB_OFF (ZBUF_FLOATS + 2 * 128 * ASTRIDE)
#define SMEM_FLOATS (ZBUF_FLOATS + 2 * 128 * ASTRIDE + 2 * 64 * ASTRIDE)
#define SMEM_BYTES (SMEM_FLOATS * 4)  // 71680
#define ABUF_BYTES (128 * ASTRIDE * 4)
#define BBUF_BYTES (64 * ASTRIDE * 4)

// -------------------- device scratch --------------------
__device__ float g_part[S_TOK * NKS * E_EXP];      // 8MB partial logits [s][ks][e]
__device__ int2  g_pack[S_TOK];                    // {gate bits, expert<<8|rank}
__device__ int   g_cntp[64 * E_EXP];               // [mtile][expert] counts
__device__ float g_me_part[64 * E_EXP];            // [mtile][expert] gate col sums
__device__ int   g_tilectr[64];                    // per-mtile ks completion
__device__ int   g_zctr;                           // grid barrier counter
__device__ int   g_phase;                          // grid barrier sense

// -------------------- packed fp32 FMA (FFMA2) --------------------
__device__ __forceinline__ void ffma2(float2& d, const float2& a, const float2& b) {
    unsigned long long dd = *(const unsigned long long*)&d;
    unsigned long long aa = *(const unsigned long long*)&a;
    unsigned long long bb = *(const unsigned long long*)&b;
    asm("fma.rn.f32x2 %0, %1, %2, %0;" : "+l"(dd) : "l"(aa), "l"(bb));
    d = *(float2*)&dd;
}

__device__ __forceinline__ unsigned smem_u32(const void* p) {
    unsigned a;
    asm("{ .reg .u64 t; cvta.to.shared.u64 t, %1; cvt.u32.u64 %0, t; }"
        : "=r"(a) : "l"(p));
    return a;
}

__device__ __forceinline__ void cpasync16(unsigned dst, const void* src) {
    asm volatile("cp.async.cg.shared.global [%0], [%1], 16;"
                 :: "r"(dst), "l"(src) : "memory");
}

// ---- ONE kernel: split-K GEMM (cp.async tiles) + paced TMA zero + softmax
//      + grid barrier + parallel scatter ----
__global__ __launch_bounds__(256, 2) void k_all(const float* __restrict__ x,
                                                const float* __restrict__ wg,
                                                float* __restrict__ out) {
    extern __shared__ float smem[];
    float* zbuf = smem;
    float* sA = smem + SA_OFF;
    float* sB = smem + SB_OFF;
    __shared__ int wcnt[4 * 64];       // per-warp per-expert counts (epilogue)
    __shared__ int spref[64];          // this block's mtile prefix (scatter)

    const int tid = threadIdx.x;
    const int lane = tid & 31, w = tid >> 5;
    const int tx = tid & 15, ty = tid >> 4;
    const int ks = blockIdx.x;
    const int mtile = blockIdx.y;
    const int m0 = mtile * 128;
    const int kbase = ks * KSLICE;
    const int b = mtile * NKS + ks;    // linear block id 0..255
    char* zdst = (char*)out + (size_t)b * ZBYTES_PER_BLOCK;

    // zero the TMA staging buffer (stays zero through the zero phase)
#pragma unroll
    for (int r = 0; r < 4; r++)
        *(float4*)&zbuf[(tid + r * 256) * 4] = make_float4(0.f, 0.f, 0.f, 0.f);

    // per-thread tile-load addressing (cp.async, no register round-trip)
    const int mA = tid >> 3, kqA = tid & 7;
    const float* xsrc = x + (size_t)(m0 + mA) * D_DIM + kbase + kqA * 4;
    const float* wsrc = wg + (size_t)mA * D_DIM + kbase + kqA * 4;
    const unsigned sAu = smem_u32(&sA[mA * ASTRIDE + kqA * 4]);
    const unsigned sBu = smem_u32(&sB[mA * ASTRIDE + kqA * 4]);

    // prologue: tile 0 via cp.async into buf 0
#pragma unroll
    for (int r = 0; r < 4; r++)
        cpasync16(sAu + r * 32 * ASTRIDE * 4, xsrc + (size_t)(r * 32) * D_DIM);
#pragma unroll
    for (int r = 0; r < 2; r++)
        cpasync16(sBu + r * 32 * ASTRIDE * 4, wsrc + (size_t)(r * 32) * D_DIM);
    asm volatile("cp.async.commit_group;" ::: "memory");
    asm volatile("cp.async.wait_group 0;" ::: "memory");
    __syncthreads();

    const unsigned zsrc = smem_u32(zbuf);
    if (tid == 0) asm volatile("fence.proxy.async;" ::: "memory");

    float2 acc[8][4];
#pragma unroll
    for (int i = 0; i < 8; i++)
#pragma unroll
        for (int j = 0; j < 4; j++) acc[i][j] = make_float2(0.f, 0.f);

    for (int it = 0; it < KSLICE / 32; it++) {
        const int buf = it & 1;
        float* cA = sA + buf * 128 * ASTRIDE;
        float* cB = sB + buf * 64 * ASTRIDE;

        // paced zeros: 8 x 16KB per iteration (128 chunks total = 2MB)
        if (tid == 0) {
#pragma unroll
            for (int c = 0; c < 8; c++) {
                char* g = zdst + (size_t)(it * 8 + c) * ZCHUNK;
                asm volatile(
                    "cp.async.bulk.global.shared::cta.bulk_group [%0], [%1], %2;"
                    :: "l"(g), "r"(zsrc), "n"(ZCHUNK) : "memory");
            }
        }

        // async prefetch of next tile directly into the other buffer
        if (it < KSLICE / 32 - 1) {
            const int koff = (it + 1) * 32;
            const unsigned nb = (buf ^ 1);
#pragma unroll
            for (int r = 0; r < 4; r++)
                cpasync16(sAu + nb * ABUF_BYTES + r * 32 * ASTRIDE * 4,
                          xsrc + (size_t)(r * 32) * D_DIM + koff);
#pragma unroll
            for (int r = 0; r < 2; r++)
                cpasync16(sBu + nb * BBUF_BYTES + r * 32 * ASTRIDE * 4,
                          wsrc + (size_t)(r * 32) * D_DIM + koff);
            asm volatile("cp.async.commit_group;" ::: "memory");
        }

#pragma unroll
        for (int kk8 = 0; kk8 < 8; kk8++) {
            float4 b4[4];
#pragma unroll
            for (int j = 0; j < 4; j++)
                b4[j] = *(const float4*)&cB[(tx + 16 * j) * ASTRIDE + kk8 * 4];
#pragma unroll
            for (int i = 0; i < 8; i++) {
                float4 a4 = *(const float4*)&cA[(ty + 16 * i) * ASTRIDE + kk8 * 4];
                const float2* ap = (const float2*)&a4;
#pragma unroll
                for (int j = 0; j < 4; j++) {
                    const float2* bp = (const float2*)&b4[j];
                    ffma2(acc[i][j], ap[0], bp[0]);
                    ffma2(acc[i][j], ap[1], bp[1]);
                }
            }
        }

        if (it < KSLICE / 32 - 1)
            asm volatile("cp.async.wait_group 0;" ::: "memory");
        __syncthreads();
    }

    if (tid == 0) asm volatile("cp.async.bulk.commit_group;" ::: "memory");

    // write partial logits: g_part[(m0+t)*4 + ks][e]
#pragma unroll
    for (int i = 0; i < 8; i++) {
        int t = m0 + ty + 16 * i;
        float* dst = g_part + ((size_t)t * NKS + ks) * E_EXP;
#pragma unroll
        for (int j = 0; j < 4; j++)
            dst[tx + 16 * j] = acc[i][j].x + acc[i][j].y;
    }

    // ---- softmax + rank epilogue: last ks-block of this mtile ----
    __shared__ int s_last;
    if (tid == 0) {
        __threadfence();
        int done = atomicAdd(&g_tilectr[mtile], 1);
        s_last = (done == NKS - 1);
        if (s_last) g_tilectr[mtile] = 0;   // reset for graph replay
    }
    __syncthreads();
    if (s_last) {
        float* sg = smem + ZBUF_FLOATS;          // 128*65 floats (over sA/sB)
        float* sq = sg + 128 * 65;               // 4*64 partial col sums
        int am = 255;                            // dummy for tid>=128 warps
        float gate = 0.f;
        wcnt[tid] = 0;
        if (tid < 128) {
            int t = m0 + tid;
            const float4* p = (const float4*)g_part + (size_t)t * 64;
            float row[64];
#pragma unroll
            for (int e4 = 0; e4 < 16; e4++) {
                float4 v0 = __ldcg(p + e4);
                float4 v1 = __ldcg(p + 16 + e4);
                float4 v2 = __ldcg(p + 32 + e4);
                float4 v3 = __ldcg(p + 48 + e4);
                row[4 * e4 + 0] = v0.x + v1.x + v2.x + v3.x;
                row[4 * e4 + 1] = v0.y + v1.y + v2.y + v3.y;
                row[4 * e4 + 2] = v0.z + v1.z + v2.z + v3.z;
                row[4 * e4 + 3] = v0.w + v1.w + v2.w + v3.w;
            }
            float mx = row[0];
            am = 0;
#pragma unroll
            for (int e = 1; e < 64; e++)
                if (row[e] > mx) { mx = row[e]; am = e; }
            float sum = 0.f;
#pragma unroll
            for (int e = 0; e < 64; e++) { row[e] = expf(row[e] - mx); sum += row[e]; }
            gate = 1.0f / sum;
#pragma unroll
            for (int e = 0; e < 64; e++) sg[tid * 65 + e] = row[e] * gate;
        }
        __syncthreads();
        // col sums for me (all 256 threads)
        {
            int col = tid & 63, q = tid >> 6;
            float cs = 0.f;
#pragma unroll 8
            for (int r = 0; r < 32; r++)
                cs += sg[(q * 32 + r) * 65 + col];
            sq[q * 64 + col] = cs;
        }
        // warp-level rank via match_any (warps 4-7 run on dummy am)
        unsigned mmask = __match_any_sync(0xffffffffu, am);
        int rin = __popc(mmask & ((1u << lane) - 1u));
        if (tid < 128 && rin == 0) wcnt[w * 64 + am] = __popc(mmask);
        __syncthreads();
        if (tid < 128) {
            int base = 0;
#pragma unroll
            for (int w2 = 0; w2 < 4; w2++)
                if (w2 < w) base += wcnt[w2 * 64 + am];
            g_pack[m0 + tid] = make_int2(__float_as_int(gate),
                                         (am << 8) | (base + rin));
        }
        if (tid < 64) {
            g_me_part[mtile * 64 + tid] =
                sq[tid] + sq[64 + tid] + sq[128 + tid] + sq[192 + tid];
            g_cntp[mtile * 64 + tid] =
                wcnt[tid] + wcnt[64 + tid] + wcnt[128 + tid] + wcnt[192 + tid];
        }
    }

    // ---- grid-wide sense-reversal barrier (all 256 blocks co-resident) ----
    // Arrival implies: this block's TMA zeros complete + its epilogue visible.
    if (tid == 0) {
        asm volatile("cp.async.bulk.wait_group 0;" ::: "memory");
        __threadfence();
        int ph = *(volatile int*)&g_phase;
        int old = atomicAdd(&g_zctr, 1);
        if (old == NBLK - 1) {
            g_zctr = 0;                       // safe: all arrived
            __threadfence();
            *(volatile int*)&g_phase = ph ^ 1;
        } else {
            while (*(volatile int*)&g_phase == ph) __nanosleep(32);
        }
    }
    __syncthreads();

    // ---- parallel scatter: 32 tokens per block, SMEM-staged counts ----
    {
        int* scnt = (int*)smem;
        {
            const int4* src = (const int4*)g_cntp;
            int4* dst4 = (int4*)smem;
#pragma unroll
            for (int r = 0; r < 4; r++)
                dst4[tid + r * 256] = __ldcg(src + tid + r * 256);
        }
        __syncthreads();

        const int M = b >> 2;              // mtile owning tokens b*32..b*32+31
        if (tid < 64) {
            int run = 0;
#pragma unroll 8
            for (int m = 0; m < M; m++) run += scnt[m * 64 + tid];
            spref[tid] = run;
        }
        __syncthreads();
        if (tid < 32) {
            int s = b * 32 + tid;
            int2 pk = __ldcg((const int2*)g_pack + s);
            int e = pk.y >> 8;
            int loc = spref[e] + (pk.y & 255);
            if (loc < CAP) {
                size_t off = (size_t)s * (E_EXP * CAP) + e * CAP + loc;
                out[1 + off] = __int_as_float(pk.x);
                out[1 + (size_t)SEC + off] = 1.0f;
            }
        }
        // block 0: l_aux + tail element (me_part staged through SMEM)
        if (b == 0) {
            float* sme = smem + SA_OFF;     // free region (4096 floats)
            {
                const float4* src = (const float4*)g_me_part;
                float4* dst4 = (float4*)sme;
#pragma unroll
                for (int r = 0; r < 4; r++)
                    dst4[tid + r * 256] = __ldcg(src + tid + r * 256);
            }
            __syncthreads();
            float v = 0.f;
            if (tid < 64) {
                float me = 0.f;
                int cnt = 0;
#pragma unroll 8
                for (int m = 0; m < 64; m++) {
                    me += sme[m * 64 + tid];
                    cnt += scnt[m * 64 + tid];
                }
                v = me * (float)cnt;
            }
#pragma unroll
            for (int o = 16; o; o >>= 1) v += __shfl_down_sync(0xffffffffu, v, o);
            __shared__ float red[2];
            if ((tid & 31) == 0 && tid < 64) red[tid >> 5] = v;
            __syncthreads();
            if (tid == 0)
                out[0] = (red[0] + red[1]) * (64.0f / (8192.0f * 8192.0f));
            if (tid == 255) out[LAST_F] = 0.0f;
        }
    }
}

// -------------------- launch: ONE kernel --------------------
extern "C" void kernel_launch(void* const* d_in, const int* in_sizes, int n_in,
                              void* d_out, int out_size) {
    const float* x  = (const float*)d_in[0];
    const float* wg = (const float*)d_in[1];
    float* out = (float*)d_out;

    static bool attr_set = false;
    if (!attr_set) {
        cudaFuncSetAttribute(k_all,
                             cudaFuncAttributeMaxDynamicSharedMemorySize,
                             SMEM_BYTES);
        attr_set = true;
    }

    k_all<<<dim3(NKS, 64), 256, SMEM_BYTES>>>(x, wg, out);
}